// round 1
// baseline (speedup 1.0000x reference)
#include <cuda_runtime.h>
#include <math.h>

// ---------------------------------------------------------------------------
// Problem constants
//   x:  [2,1024,1024] f32      (tokens T=2048, D=1024)
//   compress_neurons: [64,1024,512]   expand_neurons: [64,512,1024]
//   wq/wk/wv: [64,1024]        wo: [64,512]
//   out: [2,1024,1024] f32
// ---------------------------------------------------------------------------
#define NTOK   2048
#define DMODEL 1024
#define RANK   512
#define NHEADS 8
#define DHEAD  64
#define NC     64
#define KC     8
#define KE     4

// ---------------------------------------------------------------------------
// Device scratch (static: no allocation allowed)
// ---------------------------------------------------------------------------
__device__ float g_qkv[3 * NTOK * RANK];          // Q | K | V, [p][t][512]
__device__ float g_attn[NTOK * RANK];             // attention output [t][512]
__device__ float g_scores[16 * 1024 * 1024];      // [bh][i][j]  (64 MB)
__device__ int   g_cnt_c[3 * NC];
__device__ int   g_list_c[3 * NC * NTOK];
__device__ float g_wt_c[3 * NC * NTOK];
__device__ int   g_cnt_e[NC];
__device__ int   g_list_e[NC * NTOK];
__device__ float g_wt_e[NC * NTOK];

// ---------------------------------------------------------------------------
// Zero-init (d_out is poisoned; qkv/out are atomic-accumulated)
// ---------------------------------------------------------------------------
__global__ void k_zero(float* __restrict__ out) {
    const int idx = blockIdx.x * blockDim.x + threadIdx.x;
    const int stride = gridDim.x * blockDim.x;
    for (int i = idx; i < 3 * NTOK * RANK; i += stride) g_qkv[i] = 0.f;
    for (int i = idx; i < NTOK * DMODEL;  i += stride) out[i]   = 0.f;
    if (idx < 3 * NC) g_cnt_c[idx] = 0;
    if (idx < NC)     g_cnt_e[idx] = 0;
}

// ---------------------------------------------------------------------------
// Top-k (set semantics; softmax is order-invariant) + scatter into per-neuron
// token lists.
// ---------------------------------------------------------------------------
__device__ __forceinline__ void topk_softmax_scatter(
    const float* __restrict__ s, int K, int li_base, int t,
    int* __restrict__ cnt, int* __restrict__ lists, float* __restrict__ wts)
{
    float vals[8]; int idxs[8];
    unsigned long long taken = 0ull;
    for (int kk = 0; kk < K; ++kk) {
        float best = -1e30f; int bi = 0;
        for (int nn = 0; nn < NC; ++nn) {
            const float v = s[nn];
            if (!((taken >> nn) & 1ull) && v > best) { best = v; bi = nn; }
        }
        taken |= 1ull << bi; vals[kk] = best; idxs[kk] = bi;
    }
    const float m = vals[0];
    float ex[8]; float sum = 0.f;
    for (int kk = 0; kk < K; ++kk) { ex[kk] = expf(vals[kk] - m); sum += ex[kk]; }
    const float inv = 1.f / sum;
    for (int kk = 0; kk < K; ++kk) {
        const int li = li_base + idxs[kk];
        const int slot = atomicAdd(&cnt[li], 1);
        lists[(size_t)li * NTOK + slot] = t;
        wts [(size_t)li * NTOK + slot] = ex[kk] * inv;
    }
}

// ---------------------------------------------------------------------------
// Compress router: 8 tokens per CTA, 256 threads.
// scores[t][p][n] = x[t] . w_p[n];  then top-8 + softmax per (t,p).
// ---------------------------------------------------------------------------
__global__ __launch_bounds__(256) void k_router_c(
    const float* __restrict__ x, const float* __restrict__ wq,
    const float* __restrict__ wk, const float* __restrict__ wv)
{
    __shared__ float xs[8 * DMODEL];   // 32 KB
    __shared__ float sc[8 * 192];      // 6 KB
    const int t0 = blockIdx.x * 8;
    const int tid = threadIdx.x;
    for (int i = tid; i < 8 * DMODEL; i += 256) xs[i] = x[(size_t)t0 * DMODEL + i];
    __syncthreads();

    const int warp = tid >> 5, lane = tid & 31;
    const float* wr[3] = { wq, wk, wv };
    for (int j = warp; j < 192; j += 8) {
        const float* wrow = wr[j >> 6] + (size_t)(j & 63) * DMODEL;
        float acc[8] = {0,0,0,0,0,0,0,0};
        for (int i = lane; i < DMODEL; i += 32) {
            const float wv_ = wrow[i];
            #pragma unroll
            for (int tt = 0; tt < 8; ++tt) acc[tt] += xs[tt * DMODEL + i] * wv_;
        }
        #pragma unroll
        for (int tt = 0; tt < 8; ++tt) {
            float v = acc[tt];
            for (int o = 16; o; o >>= 1) v += __shfl_down_sync(0xffffffffu, v, o);
            if (lane == 0) sc[tt * 192 + j] = v;
        }
    }
    __syncthreads();

    if (tid < 24) {
        const int tt = tid / 3, p = tid % 3;
        topk_softmax_scatter(&sc[tt * 192 + p * 64], KC, p * 64, t0 + tt,
                             g_cnt_c, g_list_c, g_wt_c);
    }
}

// ---------------------------------------------------------------------------
// Expand router: input rows are g_attn [t][512], router wo [64,512], top-4.
// ---------------------------------------------------------------------------
__global__ __launch_bounds__(256) void k_router_e(const float* __restrict__ wo)
{
    __shared__ float xs[8 * RANK];   // 16 KB
    __shared__ float sc[8 * 64];
    const int t0 = blockIdx.x * 8;
    const int tid = threadIdx.x;
    for (int i = tid; i < 8 * RANK; i += 256) xs[i] = g_attn[(size_t)t0 * RANK + i];
    __syncthreads();

    const int warp = tid >> 5, lane = tid & 31;
    for (int j = warp; j < 64; j += 8) {
        const float* wrow = wo + (size_t)j * RANK;
        float acc[8] = {0,0,0,0,0,0,0,0};
        for (int i = lane; i < RANK; i += 32) {
            const float wv_ = wrow[i];
            #pragma unroll
            for (int tt = 0; tt < 8; ++tt) acc[tt] += xs[tt * RANK + i] * wv_;
        }
        #pragma unroll
        for (int tt = 0; tt < 8; ++tt) {
            float v = acc[tt];
            for (int o = 16; o; o >>= 1) v += __shfl_down_sync(0xffffffffu, v, o);
            if (lane == 0) sc[tt * 64 + j] = v;
        }
    }
    __syncthreads();

    if (tid < 8)
        topk_softmax_scatter(&sc[tid * 64], KE, 0, t0 + tid,
                             g_cnt_e, g_list_e, g_wt_e);
}

// ---------------------------------------------------------------------------
// Gathered GEMM with weighted atomic scatter.
// C[tok] += w * (A[tok] @ Bn)   for tok in this neuron's list.
// Tile: 64 rows x 64 cols x 16 K, 256 threads, 4x4 per thread.
// ---------------------------------------------------------------------------
template<int KA, int NOUT>
__device__ __forceinline__ void gemm_scatter_body(
    const float* __restrict__ Abase, const float* __restrict__ Bn,
    float* __restrict__ C, const int* __restrict__ tl,
    const float* __restrict__ wl, int c, int cb)
{
    __shared__ float As[64][17];
    __shared__ __align__(16) float Bs[16][64];
    __shared__ int   ts[64];
    __shared__ float ws[64];
    const int tid = threadIdx.x, tx = tid & 15, ty = tid >> 4;

    for (int row0 = 0; row0 < c; row0 += 64) {
        const int rows = min(64, c - row0);
        if (tid < 64) {
            ts[tid] = (tid < rows) ? tl[row0 + tid] : 0;
            ws[tid] = (tid < rows) ? wl[row0 + tid] : 0.f;
        }
        __syncthreads();
        float acc[4][4] = {};
        for (int k0 = 0; k0 < KA; k0 += 16) {
            #pragma unroll
            for (int e = tid; e < 1024; e += 256) {
                const int r = e >> 4, kk = e & 15;
                As[r][kk] = (r < rows) ? Abase[(size_t)ts[r] * KA + k0 + kk] : 0.f;
            }
            #pragma unroll
            for (int e = tid; e < 1024; e += 256) {
                const int kk = e >> 6, j = e & 63;
                Bs[kk][j] = Bn[(size_t)(k0 + kk) * NOUT + cb + j];
            }
            __syncthreads();
            #pragma unroll
            for (int kk = 0; kk < 16; ++kk) {
                const float a0 = As[ty*4+0][kk], a1 = As[ty*4+1][kk];
                const float a2 = As[ty*4+2][kk], a3 = As[ty*4+3][kk];
                const float4 b = *reinterpret_cast<const float4*>(&Bs[kk][tx*4]);
                acc[0][0]+=a0*b.x; acc[0][1]+=a0*b.y; acc[0][2]+=a0*b.z; acc[0][3]+=a0*b.w;
                acc[1][0]+=a1*b.x; acc[1][1]+=a1*b.y; acc[1][2]+=a1*b.z; acc[1][3]+=a1*b.w;
                acc[2][0]+=a2*b.x; acc[2][1]+=a2*b.y; acc[2][2]+=a2*b.z; acc[2][3]+=a2*b.w;
                acc[3][0]+=a3*b.x; acc[3][1]+=a3*b.y; acc[3][2]+=a3*b.z; acc[3][3]+=a3*b.w;
            }
            __syncthreads();
        }
        #pragma unroll
        for (int rr = 0; rr < 4; ++rr) {
            const int r = ty * 4 + rr;
            if (r < rows) {
                const float w = ws[r];
                float* crow = C + (size_t)ts[r] * NOUT + cb + tx * 4;
                atomicAdd(crow + 0, w * acc[rr][0]);
                atomicAdd(crow + 1, w * acc[rr][1]);
                atomicAdd(crow + 2, w * acc[rr][2]);
                atomicAdd(crow + 3, w * acc[rr][3]);
            }
        }
        __syncthreads();
    }
}

// grid: (8 coltiles, 192 lists)  list li = p*64 + n
__global__ __launch_bounds__(256) void k_gemm_compress(
    const float* __restrict__ x, const float* __restrict__ cn)
{
    const int li = blockIdx.y;
    const int n  = li & 63;
    gemm_scatter_body<DMODEL, RANK>(
        x, cn + (size_t)n * DMODEL * RANK,
        g_qkv + (size_t)(li >> 6) * NTOK * RANK,
        g_list_c + (size_t)li * NTOK, g_wt_c + (size_t)li * NTOK,
        g_cnt_c[li], blockIdx.x * 64);
}

// grid: (16 coltiles, 64 lists)
__global__ __launch_bounds__(256) void k_gemm_expand(
    const float* __restrict__ en, float* __restrict__ out)
{
    const int li = blockIdx.y;
    gemm_scatter_body<RANK, DMODEL>(
        g_attn, en + (size_t)li * RANK * DMODEL, out,
        g_list_e + (size_t)li * NTOK, g_wt_e + (size_t)li * NTOK,
        g_cnt_e[li], blockIdx.x * 64);
}

// ---------------------------------------------------------------------------
// Attention: scores = (Qh Kh^T) / 8     grid (16 jtile, 16 itile, 16 bh)
// ---------------------------------------------------------------------------
__global__ __launch_bounds__(256) void k_attn_scores()
{
    const int bh = blockIdx.z, b = bh >> 3, h = bh & 7;
    const int i0 = blockIdx.y * 64, j0 = blockIdx.x * 64;
    const float* Qb = g_qkv + (size_t)b * 1024 * RANK + h * DHEAD;
    const float* Kb = g_qkv + (size_t)NTOK * RANK + (size_t)b * 1024 * RANK + h * DHEAD;
    __shared__ float As[64][17];
    __shared__ float Bs[16][65];
    const int tid = threadIdx.x, tx = tid & 15, ty = tid >> 4;
    float acc[4][4] = {};
    for (int k0 = 0; k0 < DHEAD; k0 += 16) {
        #pragma unroll
        for (int e = tid; e < 1024; e += 256) {
            const int r = e >> 4, kk = e & 15;
            As[r][kk] = Qb[(size_t)(i0 + r) * RANK + k0 + kk];
        }
        #pragma unroll
        for (int e = tid; e < 1024; e += 256) {
            const int j = e >> 4, kk = e & 15;
            Bs[kk][j] = Kb[(size_t)(j0 + j) * RANK + k0 + kk];
        }
        __syncthreads();
        #pragma unroll
        for (int kk = 0; kk < 16; ++kk) {
            const float a0 = As[ty*4+0][kk], a1 = As[ty*4+1][kk];
            const float a2 = As[ty*4+2][kk], a3 = As[ty*4+3][kk];
            const float b0 = Bs[kk][tx*4+0], b1 = Bs[kk][tx*4+1];
            const float b2 = Bs[kk][tx*4+2], b3 = Bs[kk][tx*4+3];
            acc[0][0]+=a0*b0; acc[0][1]+=a0*b1; acc[0][2]+=a0*b2; acc[0][3]+=a0*b3;
            acc[1][0]+=a1*b0; acc[1][1]+=a1*b1; acc[1][2]+=a1*b2; acc[1][3]+=a1*b3;
            acc[2][0]+=a2*b0; acc[2][1]+=a2*b1; acc[2][2]+=a2*b2; acc[2][3]+=a2*b3;
            acc[3][0]+=a3*b0; acc[3][1]+=a3*b1; acc[3][2]+=a3*b2; acc[3][3]+=a3*b3;
        }
        __syncthreads();
    }
    float* out = g_scores + (size_t)bh * 1024 * 1024;
    #pragma unroll
    for (int rr = 0; rr < 4; ++rr)
        #pragma unroll
        for (int cc = 0; cc < 4; ++cc)
            out[(size_t)(i0 + ty*4 + rr) * 1024 + j0 + tx*4 + cc] = acc[rr][cc] * 0.125f;
}

// Row softmax over 1024 cols (mask is all-ones -> no masking). grid 16384.
__global__ __launch_bounds__(256) void k_softmax()
{
    float* p = g_scores + (size_t)blockIdx.x * 1024;
    __shared__ float red[256];
    const int tid = threadIdx.x;
    float m = -1e30f;
    for (int i = tid; i < 1024; i += 256) m = fmaxf(m, p[i]);
    red[tid] = m; __syncthreads();
    for (int s = 128; s; s >>= 1) { if (tid < s) red[tid] = fmaxf(red[tid], red[tid + s]); __syncthreads(); }
    m = red[0]; __syncthreads();
    float sum = 0.f;
    for (int i = tid; i < 1024; i += 256) { const float e = expf(p[i] - m); p[i] = e; sum += e; }
    red[tid] = sum; __syncthreads();
    for (int s = 128; s; s >>= 1) { if (tid < s) red[tid] += red[tid + s]; __syncthreads(); }
    const float inv = 1.f / red[0];
    for (int i = tid; i < 1024; i += 256) p[i] *= inv;
}

// attn_out = P @ V, written as [t][h*64+d].  grid (16 itile, 16 bh)
__global__ __launch_bounds__(256) void k_attn_pv()
{
    const int bh = blockIdx.y, b = bh >> 3, h = bh & 7;
    const int i0 = blockIdx.x * 64;
    const float* P  = g_scores + (size_t)bh * 1024 * 1024;
    const float* Vb = g_qkv + (size_t)2 * NTOK * RANK + (size_t)b * 1024 * RANK + h * DHEAD;
    __shared__ float As[64][17];
    __shared__ __align__(16) float Bs[16][64];
    const int tid = threadIdx.x, tx = tid & 15, ty = tid >> 4;
    float acc[4][4] = {};
    for (int k0 = 0; k0 < 1024; k0 += 16) {
        #pragma unroll
        for (int e = tid; e < 1024; e += 256) {
            const int r = e >> 4, kk = e & 15;
            As[r][kk] = P[(size_t)(i0 + r) * 1024 + k0 + kk];
        }
        #pragma unroll
        for (int e = tid; e < 1024; e += 256) {
            const int kk = e >> 6, j = e & 63;
            Bs[kk][j] = Vb[(size_t)(k0 + kk) * RANK + j];
        }
        __syncthreads();
        #pragma unroll
        for (int kk = 0; kk < 16; ++kk) {
            const float a0 = As[ty*4+0][kk], a1 = As[ty*4+1][kk];
            const float a2 = As[ty*4+2][kk], a3 = As[ty*4+3][kk];
            const float4 bq = *reinterpret_cast<const float4*>(&Bs[kk][tx*4]);
            acc[0][0]+=a0*bq.x; acc[0][1]+=a0*bq.y; acc[0][2]+=a0*bq.z; acc[0][3]+=a0*bq.w;
            acc[1][0]+=a1*bq.x; acc[1][1]+=a1*bq.y; acc[1][2]+=a1*bq.z; acc[1][3]+=a1*bq.w;
            acc[2][0]+=a2*bq.x; acc[2][1]+=a2*bq.y; acc[2][2]+=a2*bq.z; acc[2][3]+=a2*bq.w;
            acc[3][0]+=a3*bq.x; acc[3][1]+=a3*bq.y; acc[3][2]+=a3*bq.z; acc[3][3]+=a3*bq.w;
        }
        __syncthreads();
    }
    #pragma unroll
    for (int rr = 0; rr < 4; ++rr)
        #pragma unroll
        for (int cc = 0; cc < 4; ++cc)
            g_attn[(size_t)(b * 1024 + i0 + ty*4 + rr) * RANK + h * DHEAD + tx*4 + cc] = acc[rr][cc];
}

// ---------------------------------------------------------------------------
extern "C" void kernel_launch(void* const* d_in, const int* in_sizes, int n_in,
                              void* d_out, int out_size)
{
    const float* x  = (const float*)d_in[0];
    // d_in[1] = mask (all ones -> unused)
    const float* cn = (const float*)d_in[2];
    const float* en = (const float*)d_in[3];
    const float* wq = (const float*)d_in[4];
    const float* wk = (const float*)d_in[5];
    const float* wv = (const float*)d_in[6];
    const float* wo = (const float*)d_in[7];
    float* out = (float*)d_out;

    k_zero<<<2048, 256>>>(out);
    k_router_c<<<NTOK / 8, 256>>>(x, wq, wk, wv);
    k_gemm_compress<<<dim3(8, 192), 256>>>(x, cn);
    k_attn_scores<<<dim3(16, 16, 16), 256>>>();
    k_softmax<<<16384, 256>>>();
    k_attn_pv<<<dim3(16, 16), 256>>>();
    k_router_e<<<NTOK / 8, 256>>>(wo);
    k_gemm_expand<<<dim3(16, 64), 256>>>(en, out);
}

// round 3
// speedup vs baseline: 1.5669x; 1.5669x over previous
#include <cuda_runtime.h>
#include <math.h>

// ---------------------------------------------------------------------------
// Problem constants
// ---------------------------------------------------------------------------
#define NTOK   2048
#define DMODEL 1024
#define RANK   512
#define NHEADS 8
#define DHEAD  64
#define NC     64
#define KC     8
#define KE     4

#define APITCH 36   // words: (4g+t)%32 -> conflict-free frag loads
#define BPITCH 68
#define AOFF (64 * APITCH)   // lo-plane offset
#define BOFF (32 * BPITCH)

// ---------------------------------------------------------------------------
// Device scratch
// ---------------------------------------------------------------------------
__device__ float g_qkv[3 * NTOK * RANK];
__device__ float g_attn[NTOK * RANK];
__device__ float g_scores[16 * 1024 * 1024];
__device__ int   g_cnt_c[3 * NC];
__device__ int   g_list_c[3 * NC * NTOK];
__device__ float g_wt_c[3 * NC * NTOK];
__device__ int   g_cnt_e[NC];
__device__ int   g_list_e[NC * NTOK];
__device__ float g_wt_e[NC * NTOK];

// ---------------------------------------------------------------------------
// tf32 helpers: 3xTF32 split  f = hi + lo  (hi exact-in-f32, lo = tf32 resid)
// ---------------------------------------------------------------------------
__device__ __forceinline__ unsigned f2tf(float f) {
    unsigned u; asm("cvt.rna.tf32.f32 %0, %1;" : "=r"(u) : "f"(f)); return u;
}
__device__ __forceinline__ void st_split(unsigned* hi, unsigned* lo, float f) {
    const unsigned h = f2tf(f);
    *hi = h;
    *lo = f2tf(f - __uint_as_float(h));
}

__device__ __forceinline__ void mma8(float* c, unsigned a0, unsigned a1,
                                     unsigned a2, unsigned a3,
                                     unsigned b0, unsigned b1) {
    asm volatile(
        "mma.sync.aligned.m16n8k8.row.col.f32.tf32.tf32.f32 "
        "{%0,%1,%2,%3},{%4,%5,%6,%7},{%8,%9},{%0,%1,%2,%3};"
        : "+f"(c[0]), "+f"(c[1]), "+f"(c[2]), "+f"(c[3])
        : "r"(a0), "r"(a1), "r"(a2), "r"(a3), "r"(b0), "r"(b1));
}

// One 64x64x32 stage with 3xTF32.  Warp (wm 0..3, wn 0..1) owns m16 x n32.
__device__ __forceinline__ void compute_stage(
    const unsigned* __restrict__ As, const unsigned* __restrict__ Bs,
    float acc[4][4], int wm, int wn, int gid, int tig)
{
    #pragma unroll
    for (int ks = 0; ks < 4; ++ks) {
        const int k0 = ks * 8;
        const int r0 = (wm * 16 + gid) * APITCH + k0;
        const int r1 = (wm * 16 + gid + 8) * APITCH + k0;
        const unsigned ah0 = As[r0 + tig],        ah1 = As[r1 + tig];
        const unsigned ah2 = As[r0 + tig + 4],    ah3 = As[r1 + tig + 4];
        const unsigned al0 = As[AOFF + r0 + tig],     al1 = As[AOFF + r1 + tig];
        const unsigned al2 = As[AOFF + r0 + tig + 4], al3 = As[AOFF + r1 + tig + 4];
        #pragma unroll
        for (int t = 0; t < 4; ++t) {
            const int c0 = (k0 + tig) * BPITCH + wn * 32 + t * 8 + gid;
            const int c1 = (k0 + tig + 4) * BPITCH + wn * 32 + t * 8 + gid;
            const unsigned bh0 = Bs[c0],        bh1 = Bs[c1];
            const unsigned bl0 = Bs[BOFF + c0], bl1 = Bs[BOFF + c1];
            mma8(acc[t], ah0, ah1, ah2, ah3, bl0, bl1);   // hi*lo
            mma8(acc[t], al0, al1, al2, al3, bh0, bh1);   // lo*hi
            mma8(acc[t], ah0, ah1, ah2, ah3, bh0, bh1);   // hi*hi (last: biggest term)
        }
    }
}

// ---------------------------------------------------------------------------
__global__ void k_zero(float* __restrict__ out) {
    const int idx = blockIdx.x * blockDim.x + threadIdx.x;
    const int stride = gridDim.x * blockDim.x;
    for (int i = idx; i < 3 * NTOK * RANK; i += stride) g_qkv[i] = 0.f;
    for (int i = idx; i < NTOK * DMODEL;  i += stride) out[i]   = 0.f;
    if (idx < 3 * NC) g_cnt_c[idx] = 0;
    if (idx < NC)     g_cnt_e[idx] = 0;
}

// ---------------------------------------------------------------------------
// Top-k + softmax + scatter (exact fp32; set semantics)
// ---------------------------------------------------------------------------
__device__ __forceinline__ void topk_softmax_scatter(
    const float* __restrict__ s, int K, int li_base, int t,
    int* __restrict__ cnt, int* __restrict__ lists, float* __restrict__ wts)
{
    float vals[8]; int idxs[8];
    unsigned long long taken = 0ull;
    for (int kk = 0; kk < K; ++kk) {
        float best = -1e30f; int bi = 0;
        for (int nn = 0; nn < NC; ++nn) {
            const float v = s[nn];
            if (!((taken >> nn) & 1ull) && v > best) { best = v; bi = nn; }
        }
        taken |= 1ull << bi; vals[kk] = best; idxs[kk] = bi;
    }
    const float m = vals[0];
    float ex[8]; float sum = 0.f;
    for (int kk = 0; kk < K; ++kk) { ex[kk] = expf(vals[kk] - m); sum += ex[kk]; }
    const float inv = 1.f / sum;
    for (int kk = 0; kk < K; ++kk) {
        const int li = li_base + idxs[kk];
        const int slot = atomicAdd(&cnt[li], 1);
        lists[(size_t)li * NTOK + slot] = t;
        wts [(size_t)li * NTOK + slot] = ex[kk] * inv;
    }
}

// ---------------------------------------------------------------------------
__global__ __launch_bounds__(256) void k_router_c(
    const float* __restrict__ x, const float* __restrict__ wq,
    const float* __restrict__ wk, const float* __restrict__ wv)
{
    __shared__ float xs[8 * DMODEL];
    __shared__ float sc[8 * 192];
    const int t0 = blockIdx.x * 8;
    const int tid = threadIdx.x;
    for (int i = tid; i < 8 * DMODEL; i += 256) xs[i] = x[(size_t)t0 * DMODEL + i];
    __syncthreads();

    const int warp = tid >> 5, lane = tid & 31;
    const float* wr[3] = { wq, wk, wv };
    for (int j = warp; j < 192; j += 8) {
        const float* wrow = wr[j >> 6] + (size_t)(j & 63) * DMODEL;
        float acc[8] = {0,0,0,0,0,0,0,0};
        for (int i = lane; i < DMODEL; i += 32) {
            const float wv_ = wrow[i];
            #pragma unroll
            for (int tt = 0; tt < 8; ++tt) acc[tt] += xs[tt * DMODEL + i] * wv_;
        }
        #pragma unroll
        for (int tt = 0; tt < 8; ++tt) {
            float v = acc[tt];
            for (int o = 16; o; o >>= 1) v += __shfl_down_sync(0xffffffffu, v, o);
            if (lane == 0) sc[tt * 192 + j] = v;
        }
    }
    __syncthreads();

    if (tid < 24) {
        const int tt = tid / 3, p = tid % 3;
        topk_softmax_scatter(&sc[tt * 192 + p * 64], KC, p * 64, t0 + tt,
                             g_cnt_c, g_list_c, g_wt_c);
    }
}

__global__ __launch_bounds__(256) void k_router_e(const float* __restrict__ wo)
{
    __shared__ float xs[8 * RANK];
    __shared__ float sc[8 * 64];
    const int t0 = blockIdx.x * 8;
    const int tid = threadIdx.x;
    for (int i = tid; i < 8 * RANK; i += 256) xs[i] = g_attn[(size_t)t0 * RANK + i];
    __syncthreads();

    const int warp = tid >> 5, lane = tid & 31;
    for (int j = warp; j < 64; j += 8) {
        const float* wrow = wo + (size_t)j * RANK;
        float acc[8] = {0,0,0,0,0,0,0,0};
        for (int i = lane; i < RANK; i += 32) {
            const float wv_ = wrow[i];
            #pragma unroll
            for (int tt = 0; tt < 8; ++tt) acc[tt] += xs[tt * RANK + i] * wv_;
        }
        #pragma unroll
        for (int tt = 0; tt < 8; ++tt) {
            float v = acc[tt];
            for (int o = 16; o; o >>= 1) v += __shfl_down_sync(0xffffffffu, v, o);
            if (lane == 0) sc[tt * 64 + j] = v;
        }
    }
    __syncthreads();

    if (tid < 8)
        topk_softmax_scatter(&sc[tid * 64], KE, 0, t0 + tid,
                             g_cnt_e, g_list_e, g_wt_e);
}

// ---------------------------------------------------------------------------
// Gathered 3xTF32 MMA GEMM with weighted atomic scatter.
// ---------------------------------------------------------------------------
template<int KA, int NOUT>
__device__ __forceinline__ void gemm_scatter_mma(
    const float* __restrict__ Abase, const float* __restrict__ Bn,
    float* __restrict__ C, const int* __restrict__ tl,
    const float* __restrict__ wl, int c, int cb)
{
    __shared__ unsigned As[2 * 64 * APITCH];
    __shared__ unsigned Bs[2 * 32 * BPITCH];
    __shared__ int   ts[64];
    __shared__ float ws[64];
    const int tid = threadIdx.x, lane = tid & 31, warp = tid >> 5;
    const int wm = warp & 3, wn = warp >> 2;
    const int gid = lane >> 2, tig = lane & 3;

    for (int row0 = 0; row0 < c; row0 += 64) {
        const int rows = min(64, c - row0);
        __syncthreads();               // prior epilogue done reading ts/ws
        if (tid < 64) {
            ts[tid] = (tid < rows) ? tl[row0 + tid] : 0;
            ws[tid] = (tid < rows) ? wl[row0 + tid] : 0.f;
        }
        float acc[4][4] = {};
        for (int k0 = 0; k0 < KA; k0 += 32) {
            __syncthreads();
            #pragma unroll
            for (int e = tid; e < 512; e += 256) {      // A: 64 x 32
                const int r = e >> 3, q = e & 7;
                const float4 v = *reinterpret_cast<const float4*>(
                    Abase + (size_t)ts[r] * KA + k0 + q * 4);
                unsigned* h = &As[r * APITCH + q * 4];
                st_split(h + 0, h + AOFF + 0, v.x);
                st_split(h + 1, h + AOFF + 1, v.y);
                st_split(h + 2, h + AOFF + 2, v.z);
                st_split(h + 3, h + AOFF + 3, v.w);
            }
            #pragma unroll
            for (int e = tid; e < 512; e += 256) {      // B: 32 x 64
                const int kk = e >> 4, q = e & 15;
                const float4 v = *reinterpret_cast<const float4*>(
                    Bn + (size_t)(k0 + kk) * NOUT + cb + q * 4);
                unsigned* h = &Bs[kk * BPITCH + q * 4];
                st_split(h + 0, h + BOFF + 0, v.x);
                st_split(h + 1, h + BOFF + 1, v.y);
                st_split(h + 2, h + BOFF + 2, v.z);
                st_split(h + 3, h + BOFF + 3, v.w);
            }
            __syncthreads();
            compute_stage(As, Bs, acc, wm, wn, gid, tig);
        }
        #pragma unroll
        for (int i = 0; i < 4; ++i) {
            const int r = wm * 16 + gid + ((i >> 1) ? 8 : 0);
            if (r < rows) {
                const float w = ws[r];
                float* crow = C + (size_t)ts[r] * NOUT + cb;
                #pragma unroll
                for (int t = 0; t < 4; ++t)
                    atomicAdd(&crow[wn * 32 + t * 8 + tig * 2 + (i & 1)],
                              w * acc[t][i]);
            }
        }
    }
}

__global__ __launch_bounds__(256) void k_gemm_compress(
    const float* __restrict__ x, const float* __restrict__ cn)
{
    const int li = blockIdx.y;
    const int n  = li & 63;
    gemm_scatter_mma<DMODEL, RANK>(
        x, cn + (size_t)n * DMODEL * RANK,
        g_qkv + (size_t)(li >> 6) * NTOK * RANK,
        g_list_c + (size_t)li * NTOK, g_wt_c + (size_t)li * NTOK,
        g_cnt_c[li], blockIdx.x * 64);
}

__global__ __launch_bounds__(256) void k_gemm_expand(
    const float* __restrict__ en, float* __restrict__ out)
{
    const int li = blockIdx.y;
    gemm_scatter_mma<RANK, DMODEL>(
        g_attn, en + (size_t)li * RANK * DMODEL, out,
        g_list_e + (size_t)li * NTOK, g_wt_e + (size_t)li * NTOK,
        g_cnt_e[li], blockIdx.x * 64);
}

// ---------------------------------------------------------------------------
// Attention scores = (Qh Kh^T)/8 via 3xTF32 MMA. grid (16 j, 16 i, 16 bh)
// ---------------------------------------------------------------------------
__global__ __launch_bounds__(256) void k_attn_scores()
{
    const int bh = blockIdx.z, b = bh >> 3, h = bh & 7;
    const int i0 = blockIdx.y * 64, j0 = blockIdx.x * 64;
    const float* Qb = g_qkv + (size_t)b * 1024 * RANK + h * DHEAD;
    const float* Kb = g_qkv + (size_t)NTOK * RANK + (size_t)b * 1024 * RANK + h * DHEAD;
    __shared__ unsigned As[2 * 64 * APITCH];
    __shared__ unsigned Bs[2 * 32 * BPITCH];
    const int tid = threadIdx.x, lane = tid & 31, warp = tid >> 5;
    const int wm = warp & 3, wn = warp >> 2;
    const int gid = lane >> 2, tig = lane & 3;

    float acc[4][4] = {};
    for (int k0 = 0; k0 < DHEAD; k0 += 32) {
        __syncthreads();
        #pragma unroll
        for (int e = tid; e < 512; e += 256) {          // A = Q rows
            const int r = e >> 3, q = e & 7;
            const float4 v = *reinterpret_cast<const float4*>(
                Qb + (size_t)(i0 + r) * RANK + k0 + q * 4);
            unsigned* hd = &As[r * APITCH + q * 4];
            st_split(hd + 0, hd + AOFF + 0, v.x);
            st_split(hd + 1, hd + AOFF + 1, v.y);
            st_split(hd + 2, hd + AOFF + 2, v.z);
            st_split(hd + 3, hd + AOFF + 3, v.w);
        }
        #pragma unroll
        for (int e = tid; e < 512; e += 256) {          // B[k][n] = K[j0+n][k]
            const int n = e >> 3, q = e & 7;
            const float4 v = *reinterpret_cast<const float4*>(
                Kb + (size_t)(j0 + n) * RANK + k0 + q * 4);
            st_split(&Bs[(q*4+0)*BPITCH + n], &Bs[BOFF + (q*4+0)*BPITCH + n], v.x);
            st_split(&Bs[(q*4+1)*BPITCH + n], &Bs[BOFF + (q*4+1)*BPITCH + n], v.y);
            st_split(&Bs[(q*4+2)*BPITCH + n], &Bs[BOFF + (q*4+2)*BPITCH + n], v.z);
            st_split(&Bs[(q*4+3)*BPITCH + n], &Bs[BOFF + (q*4+3)*BPITCH + n], v.w);
        }
        __syncthreads();
        compute_stage(As, Bs, acc, wm, wn, gid, tig);
    }
    float* outp = g_scores + (size_t)bh * 1024 * 1024;
    #pragma unroll
    for (int i = 0; i < 4; ++i) {
        const int r = i0 + wm * 16 + gid + ((i >> 1) ? 8 : 0);
        #pragma unroll
        for (int t = 0; t < 4; ++t)
            outp[(size_t)r * 1024 + j0 + wn * 32 + t * 8 + tig * 2 + (i & 1)] =
                acc[t][i] * 0.125f;
    }
}

// ---------------------------------------------------------------------------
__global__ __launch_bounds__(256) void k_softmax()
{
    float* p = g_scores + (size_t)blockIdx.x * 1024;
    __shared__ float red[256];
    const int tid = threadIdx.x;
    float m = -1e30f;
    for (int i = tid; i < 1024; i += 256) m = fmaxf(m, p[i]);
    red[tid] = m; __syncthreads();
    for (int s = 128; s; s >>= 1) { if (tid < s) red[tid] = fmaxf(red[tid], red[tid + s]); __syncthreads(); }
    m = red[0]; __syncthreads();
    float sum = 0.f;
    for (int i = tid; i < 1024; i += 256) { const float e = expf(p[i] - m); p[i] = e; sum += e; }
    red[tid] = sum; __syncthreads();
    for (int s = 128; s; s >>= 1) { if (tid < s) red[tid] += red[tid + s]; __syncthreads(); }
    const float inv = 1.f / red[0];
    for (int i = tid; i < 1024; i += 256) p[i] *= inv;
}

// ---------------------------------------------------------------------------
// attn_out = P @ V via 3xTF32 MMA.  grid (16 itile, 16 bh)
// ---------------------------------------------------------------------------
__global__ __launch_bounds__(256) void k_attn_pv()
{
    const int bh = blockIdx.y, b = bh >> 3, h = bh & 7;
    const int i0 = blockIdx.x * 64;
    const float* P  = g_scores + (size_t)bh * 1024 * 1024;
    const float* Vb = g_qkv + (size_t)2 * NTOK * RANK + (size_t)b * 1024 * RANK + h * DHEAD;
    __shared__ unsigned As[2 * 64 * APITCH];
    __shared__ unsigned Bs[2 * 32 * BPITCH];
    const int tid = threadIdx.x, lane = tid & 31, warp = tid >> 5;
    const int wm = warp & 3, wn = warp >> 2;
    const int gid = lane >> 2, tig = lane & 3;

    float acc[4][4] = {};
    for (int k0 = 0; k0 < 1024; k0 += 32) {
        __syncthreads();
        #pragma unroll
        for (int e = tid; e < 512; e += 256) {          // A = P rows
            const int r = e >> 3, q = e & 7;
            const float4 v = *reinterpret_cast<const float4*>(
                P + (size_t)(i0 + r) * 1024 + k0 + q * 4);
            unsigned* hd = &As[r * APITCH + q * 4];
            st_split(hd + 0, hd + AOFF + 0, v.x);
            st_split(hd + 1, hd + AOFF + 1, v.y);
            st_split(hd + 2, hd + AOFF + 2, v.z);
            st_split(hd + 3, hd + AOFF + 3, v.w);
        }
        #pragma unroll
        for (int e = tid; e < 512; e += 256) {          // B = V rows (k-major)
            const int kk = e >> 4, q = e & 15;
            const float4 v = *reinterpret_cast<const float4*>(
                Vb + (size_t)(k0 + kk) * RANK + q * 4);
            unsigned* hd = &Bs[kk * BPITCH + q * 4];
            st_split(hd + 0, hd + BOFF + 0, v.x);
            st_split(hd + 1, hd + BOFF + 1, v.y);
            st_split(hd + 2, hd + BOFF + 2, v.z);
            st_split(hd + 3, hd + BOFF + 3, v.w);
        }
        __syncthreads();
        compute_stage(As, Bs, acc, wm, wn, gid, tig);
    }
    #pragma unroll
    for (int i = 0; i < 4; ++i) {
        const int r = b * 1024 + i0 + wm * 16 + gid + ((i >> 1) ? 8 : 0);
        #pragma unroll
        for (int t = 0; t < 4; ++t)
            g_attn[(size_t)r * RANK + h * DHEAD + wn * 32 + t * 8 + tig * 2 + (i & 1)] =
                acc[t][i];
    }
}

// ---------------------------------------------------------------------------
extern "C" void kernel_launch(void* const* d_in, const int* in_sizes, int n_in,
                              void* d_out, int out_size)
{
    const float* x  = (const float*)d_in[0];
    const float* cn = (const float*)d_in[2];
    const float* en = (const float*)d_in[3];
    const float* wq = (const float*)d_in[4];
    const float* wk = (const float*)d_in[5];
    const float* wv = (const float*)d_in[6];
    const float* wo = (const float*)d_in[7];
    float* out = (float*)d_out;

    k_zero<<<2048, 256>>>(out);
    k_router_c<<<NTOK / 8, 256>>>(x, wq, wk, wv);
    k_gemm_compress<<<dim3(8, 192), 256>>>(x, cn);
    k_attn_scores<<<dim3(16, 16, 16), 256>>>();
    k_softmax<<<16384, 256>>>();
    k_attn_pv<<<dim3(16, 16), 256>>>();
    k_router_e<<<NTOK / 8, 256>>>(wo);
    k_gemm_expand<<<dim3(16, 64), 256>>>(en, out);
}